// round 10
// baseline (speedup 1.0000x reference)
#include <cuda_runtime.h>
#include <cstdint>

// DynamicTopGate, fused single-kernel version (round 10).
//
// Round-9 lesson (regression): 4 rows/warp blew the ~70-reg main-loop budget
// and lost load batching. This round reverts to the proven round-8 structure
// (2 rows/warp, 20 warps/SM, unroll-4 load batching) and adds:
//   1. f32x2 packed FMAs at 2 rows (acc stays 32 regs, FFMA instrs halved).
//   2. Epilogue fused into the GEMM tail (lanes 0-1), deleting the dependent
//      ~14us second launch and the scratch roundtrip.

#define IN_DIM 2048
#define NE     16

typedef unsigned long long u64;

// Packed f32x2 FMA (Blackwell): 2 FMAs per instruction.
__device__ __forceinline__ u64 ffma2(u64 a, u64 b, u64 c) {
    u64 d;
    asm("fma.rn.f32x2 %0, %1, %2, %3;" : "=l"(d) : "l"(a), "l"(b), "l"(c));
    return d;
}
__device__ __forceinline__ void unpack2(u64 a, float& lo, float& hi) {
    asm("mov.b64 {%0, %1}, %2;" : "=f"(lo), "=f"(hi) : "l"(a));
}

// Descending compare-exchange, stable (index-ascending) tie-break,
// matching jnp.argsort(-logits).
#define CE(a, b) do {                                                \
    float va = v[a], vb = v[b]; int ia = id[a], ib = id[b];          \
    bool sw = (vb > va) || (vb == va && ib < ia);                    \
    v[a] = sw ? vb : va; v[b] = sw ? va : vb;                        \
    id[a] = sw ? ib : ia; id[b] = sw ? ia : ib;                      \
} while (0);

__global__ void __launch_bounds__(128, 5)
gate_kernel(const float* __restrict__ x, const float* __restrict__ W1,
            const float* __restrict__ W2, float* __restrict__ out, int B)
{
    const int lane = threadIdx.x & 31;
    const int gw   = blockIdx.x * 4 + (threadIdx.x >> 5);
    const int row0 = gw * 2;
    if (row0 >= B) return;

    const float4* x0 = reinterpret_cast<const float4*>(x + (size_t)row0 * IN_DIM) + lane;
    const float4* x1 = x0 + (IN_DIM / 4);
    const float4* wp = reinterpret_cast<const float4*>(W1) + lane;

    // Packed (even-col, odd-col) partial sums: 2 rows x 16 experts = 32 regs.
    u64 acc0[NE], acc1[NE];
    #pragma unroll
    for (int e = 0; e < NE; ++e) { acc0[e] = 0ull; acc1[e] = 0ull; }

    // 16 chunks of 128 columns; unroll 4 so ptxas front-batches the x loads
    // (8 LDG.128 per body) -- the configuration round 8 proved out.
    #pragma unroll 4
    for (int c = 0; c < IN_DIM / 128; ++c) {
        float4 a0 = __ldcs(x0 + c * 32);     // stream x, keep W1 in L1
        float4 a1 = __ldcs(x1 + c * 32);
        const u64* a0p = reinterpret_cast<const u64*>(&a0);
        const u64* a1p = reinterpret_cast<const u64*>(&a1);
        #pragma unroll
        for (int e = 0; e < NE; ++e) {
            float4 w = __ldg(wp + e * (IN_DIM / 4) + c * 32);   // W1 L1-resident
            const u64* wpk = reinterpret_cast<const u64*>(&w);
            acc0[e] = ffma2(a0p[0], wpk[0], acc0[e]);
            acc0[e] = ffma2(a0p[1], wpk[1], acc0[e]);
            acc1[e] = ffma2(a1p[0], wpk[0], acc1[e]);
            acc1[e] = ffma2(a1p[1], wpk[1], acc1[e]);
        }
    }

    // Fold packed halves and butterfly-reduce across the warp.
    float s0[NE], s1[NE];
    #pragma unroll
    for (int e = 0; e < NE; ++e) {
        float lo, hi;
        unpack2(acc0[e], lo, hi); s0[e] = lo + hi;
        unpack2(acc1[e], lo, hi); s1[e] = lo + hi;
        #pragma unroll
        for (int off = 16; off > 0; off >>= 1) {
            s0[e] += __shfl_xor_sync(0xffffffffu, s0[e], off);
            s1[e] += __shfl_xor_sync(0xffffffffu, s1[e], off);
        }
    }

    // ---- fused epilogue: lane 0 -> row0, lane 1 -> row0+1 ----
    if (lane < 2) {
        const int row = row0 + lane;

        float h[NE];
        #pragma unroll
        for (int e = 0; e < NE; ++e)
            h[e] = tanhf(lane == 0 ? s0[e] : s1[e]);

        // logits[f] = (sum_e h[e] * W2[f, e]) / 0.7
        float v[NE]; int id[NE];
        const float4* W2v = reinterpret_cast<const float4*>(W2);
        #pragma unroll
        for (int f = 0; f < NE; ++f) {
            float s = 0.0f;
            #pragma unroll
            for (int q = 0; q < NE / 4; ++q) {
                float4 w = __ldg(W2v + f * (NE / 4) + q);
                s = fmaf(h[4 * q + 0], w.x, s);
                s = fmaf(h[4 * q + 1], w.y, s);
                s = fmaf(h[4 * q + 2], w.z, s);
                s = fmaf(h[4 * q + 3], w.w, s);
            }
            v[f] = s / 0.7f;
            id[f] = f;
        }

        // Batcher odd-even mergesort, n=16, 63 comparators, descending.
        CE(0,1) CE(2,3) CE(4,5) CE(6,7) CE(8,9) CE(10,11) CE(12,13) CE(14,15)
        CE(0,2) CE(1,3) CE(4,6) CE(5,7) CE(8,10) CE(9,11) CE(12,14) CE(13,15)
        CE(1,2) CE(5,6) CE(9,10) CE(13,14)
        CE(0,4) CE(1,5) CE(2,6) CE(3,7) CE(8,12) CE(9,13) CE(10,14) CE(11,15)
        CE(2,4) CE(3,5) CE(10,12) CE(11,13)
        CE(1,2) CE(3,4) CE(5,6) CE(9,10) CE(11,12) CE(13,14)
        CE(0,8) CE(1,9) CE(2,10) CE(3,11) CE(4,12) CE(5,13) CE(6,14) CE(7,15)
        CE(4,8) CE(5,9) CE(6,10) CE(7,11)
        CE(2,4) CE(3,5) CE(6,8) CE(7,9) CE(10,12) CE(11,13)
        CE(1,2) CE(3,4) CE(5,6) CE(7,8) CE(9,10) CE(11,12) CE(13,14)

        // Softmax over sorted logits (max = v[0]).
        float m = v[0];
        float p[NE]; float ssum = 0.0f;
        #pragma unroll
        for (int e = 0; e < NE; ++e) { p[e] = expf(v[e] - m); ssum += p[e]; }
        float inv = 1.0f / ssum;
        #pragma unroll
        for (int e = 0; e < NE; ++e) p[e] *= inv;

        // k from cumulative probability.
        int k = NE;
        float cum = 0.0f;
        #pragma unroll
        for (int e = 0; e < NE; ++e) {
            cum += p[e];
            if (k == NE && cum >= 0.92f) k = e + 1;
        }
        float p1 = p[0], p2 = p[1], p3 = p[2];
        if (p1 >= 0.46f && (p1 - p2) >= 0.1f) k = 1;
        if (k > 2 && ((p1 + p2) >= 0.82f || p3 <= 0.12f || (p2 - p3) <= 0.03f)) k = 2;
        if (k < 1) k = 1;
        if (k > 3) k = 3;

        float* oidx  = out;
        float* osc   = out + (size_t)B * 8;
        float* omask = out + (size_t)B * 16;
        float* okv   = out + (size_t)B * 24;
        #pragma unroll
        for (int j = 0; j < 8; ++j) {
            float msk = (j < k) ? 1.0f : 0.0f;
            oidx[row * 8 + j]  = (float)id[j];
            osc[row * 8 + j]   = p[j] * msk;
            omask[row * 8 + j] = msk;
        }
        okv[row] = (float)k;
    }
}

extern "C" void kernel_launch(void* const* d_in, const int* in_sizes, int n_in,
                              void* d_out, int out_size)
{
    const float* x  = (const float*)d_in[0];
    const float* W1 = (const float*)d_in[1];
    const float* W2 = (const float*)d_in[2];
    float* out = (float*)d_out;

    int B = in_sizes[0] / IN_DIM;                 // 16384

    // 4 warps/block, 2 rows/warp -> 8 rows/block.
    int blocks = (B + 7) / 8;                     // 2048
    gate_kernel<<<blocks, 128>>>(x, W1, W2, out, B);
}

// round 11
// speedup vs baseline: 2.2155x; 2.2155x over previous
#include <cuda_runtime.h>
#include <cstdint>

// DynamicTopGate, fused single-kernel (round 11).
//
// Established invariants:
//  - inline-asm f32x2 inner loops cap at ~1 TB/s (scheduling barrier + reg
//    pairing): NEVER use them. Plain-C fmaf loop (round 8) reached 2.9 TB/s.
//  - ~70-reg main-loop budget + 20 warps/SM ((128,5)) is the proven config.
// This round: round-8's exact scalar GEMM loop, with the per-row epilogue
// fused into the kernel tail on lanes 0-1 (round 10 proved fusion correctness;
// it was only slow because of the asm loop). Deletes the dependent ~14us
// epilogue launch and the 1MB scratch roundtrip.

#define IN_DIM 2048
#define NE     16

// Descending compare-exchange, stable (index-ascending) tie-break,
// matching jnp.argsort(-logits).
#define CE(a, b) do {                                                \
    float va = v[a], vb = v[b]; int ia = id[a], ib = id[b];          \
    bool sw = (vb > va) || (vb == va && ib < ia);                    \
    v[a] = sw ? vb : va; v[b] = sw ? va : vb;                        \
    id[a] = sw ? ib : ia; id[b] = sw ? ia : ib;                      \
} while (0);

__global__ void __launch_bounds__(128, 5)
gate_kernel(const float* __restrict__ x, const float* __restrict__ W1,
            const float* __restrict__ W2, float* __restrict__ out, int B)
{
    const int lane = threadIdx.x & 31;
    const int gw   = blockIdx.x * 4 + (threadIdx.x >> 5);
    const int row0 = gw * 2;
    if (row0 >= B) return;

    const float4* x0 = reinterpret_cast<const float4*>(x + (size_t)row0 * IN_DIM) + lane;
    const float4* x1 = x0 + (IN_DIM / 4);
    const float4* wp = reinterpret_cast<const float4*>(W1) + lane;

    float acc0[NE], acc1[NE];
    #pragma unroll
    for (int e = 0; e < NE; ++e) { acc0[e] = 0.0f; acc1[e] = 0.0f; }

    // Round-8 proven loop: 16 chunks of 128 columns, unroll 4 so ptxas
    // front-batches 8 LDG.128 x-loads per body. DO NOT add asm here.
    #pragma unroll 4
    for (int c = 0; c < IN_DIM / 128; ++c) {
        float4 a0 = __ldcs(x0 + c * 32);     // stream x: keep W1 in L1
        float4 a1 = __ldcs(x1 + c * 32);
        #pragma unroll
        for (int e = 0; e < NE; ++e) {
            float4 w = __ldg(wp + e * (IN_DIM / 4) + c * 32);   // W1 L1-resident
            acc0[e] = fmaf(a0.x, w.x, fmaf(a0.y, w.y,
                      fmaf(a0.z, w.z, fmaf(a0.w, w.w, acc0[e]))));
            acc1[e] = fmaf(a1.x, w.x, fmaf(a1.y, w.y,
                      fmaf(a1.z, w.z, fmaf(a1.w, w.w, acc1[e]))));
        }
    }

    // Butterfly-reduce each accumulator across the warp (all lanes get sums).
    #pragma unroll
    for (int e = 0; e < NE; ++e) {
        #pragma unroll
        for (int off = 16; off > 0; off >>= 1) {
            acc0[e] += __shfl_xor_sync(0xffffffffu, acc0[e], off);
            acc1[e] += __shfl_xor_sync(0xffffffffu, acc1[e], off);
        }
    }

    // ---- fused epilogue: lane 0 -> row0, lane 1 -> row0+1 ----
    if (lane < 2) {
        const int row = row0 + lane;

        float h[NE];
        #pragma unroll
        for (int e = 0; e < NE; ++e)
            h[e] = tanhf(lane == 0 ? acc0[e] : acc1[e]);

        // logits[f] = (sum_e h[e] * W2[f, e]) / 0.7
        float v[NE]; int id[NE];
        const float4* W2v = reinterpret_cast<const float4*>(W2);
        #pragma unroll
        for (int f = 0; f < NE; ++f) {
            float s = 0.0f;
            #pragma unroll
            for (int q = 0; q < NE / 4; ++q) {
                float4 w = __ldg(W2v + f * (NE / 4) + q);
                s = fmaf(h[4 * q + 0], w.x, s);
                s = fmaf(h[4 * q + 1], w.y, s);
                s = fmaf(h[4 * q + 2], w.z, s);
                s = fmaf(h[4 * q + 3], w.w, s);
            }
            v[f] = s / 0.7f;
            id[f] = f;
        }

        // Batcher odd-even mergesort, n=16, 63 comparators, descending.
        CE(0,1) CE(2,3) CE(4,5) CE(6,7) CE(8,9) CE(10,11) CE(12,13) CE(14,15)
        CE(0,2) CE(1,3) CE(4,6) CE(5,7) CE(8,10) CE(9,11) CE(12,14) CE(13,15)
        CE(1,2) CE(5,6) CE(9,10) CE(13,14)
        CE(0,4) CE(1,5) CE(2,6) CE(3,7) CE(8,12) CE(9,13) CE(10,14) CE(11,15)
        CE(2,4) CE(3,5) CE(10,12) CE(11,13)
        CE(1,2) CE(3,4) CE(5,6) CE(9,10) CE(11,12) CE(13,14)
        CE(0,8) CE(1,9) CE(2,10) CE(3,11) CE(4,12) CE(5,13) CE(6,14) CE(7,15)
        CE(4,8) CE(5,9) CE(6,10) CE(7,11)
        CE(2,4) CE(3,5) CE(6,8) CE(7,9) CE(10,12) CE(11,13)
        CE(1,2) CE(3,4) CE(5,6) CE(7,8) CE(9,10) CE(11,12) CE(13,14)

        // Softmax over sorted logits (max = v[0]).
        float m = v[0];
        float p[NE]; float ssum = 0.0f;
        #pragma unroll
        for (int e = 0; e < NE; ++e) { p[e] = expf(v[e] - m); ssum += p[e]; }
        float inv = 1.0f / ssum;
        #pragma unroll
        for (int e = 0; e < NE; ++e) p[e] *= inv;

        // k from cumulative probability.
        int k = NE;
        float cum = 0.0f;
        #pragma unroll
        for (int e = 0; e < NE; ++e) {
            cum += p[e];
            if (k == NE && cum >= 0.92f) k = e + 1;
        }
        float p1 = p[0], p2 = p[1], p3 = p[2];
        if (p1 >= 0.46f && (p1 - p2) >= 0.1f) k = 1;
        if (k > 2 && ((p1 + p2) >= 0.82f || p3 <= 0.12f || (p2 - p3) <= 0.03f)) k = 2;
        if (k < 1) k = 1;
        if (k > 3) k = 3;

        float* oidx  = out;
        float* osc   = out + (size_t)B * 8;
        float* omask = out + (size_t)B * 16;
        float* okv   = out + (size_t)B * 24;
        #pragma unroll
        for (int j = 0; j < 8; ++j) {
            float msk = (j < k) ? 1.0f : 0.0f;
            oidx[row * 8 + j]  = (float)id[j];
            osc[row * 8 + j]   = p[j] * msk;
            omask[row * 8 + j] = msk;
        }
        okv[row] = (float)k;
    }
}

extern "C" void kernel_launch(void* const* d_in, const int* in_sizes, int n_in,
                              void* d_out, int out_size)
{
    const float* x  = (const float*)d_in[0];
    const float* W1 = (const float*)d_in[1];
    const float* W2 = (const float*)d_in[2];
    float* out = (float*)d_out;

    int B = in_sizes[0] / IN_DIM;                 // 16384

    // 4 warps/block, 2 rows/warp -> 8 rows/block.
    int blocks = (B + 7) / 8;                     // 2048
    gate_kernel<<<blocks, 128>>>(x, W1, W2, out, B);
}

// round 12
// speedup vs baseline: 2.4685x; 1.1142x over previous
#include <cuda_runtime.h>
#include <cstdint>

// DynamicTopGate, fused single-kernel, warp-parallel epilogue (round 12).
//
// Invariants (hard-won):
//  - NO inline-asm in the GEMM loop (f32x2 asm caps BW at ~1 TB/s).
//  - Round-8 scalar loop config is protected: 2 rows/warp, (128,5),
//    unroll 4, __ldcs x / __ldg W1.  It reaches 2.9 TB/s effective.
//  - Round-11: fusing a SERIAL epilogue costs ~11-17us of issue budget.
// This round: same GEMM loop, but the epilogue runs warp-parallel
// (lane-per-expert, bitonic argsort via shfl on packed keys), ~150 instr.

#define IN_DIM 2048
#define NE     16

typedef unsigned long long u64;

__global__ void __launch_bounds__(128, 5)
gate_kernel(const float* __restrict__ x, const float* __restrict__ W1,
            const float* __restrict__ W2, float* __restrict__ out, int B)
{
    const int lane = threadIdx.x & 31;
    const int gw   = blockIdx.x * 4 + (threadIdx.x >> 5);
    const int row0 = gw * 2;
    if (row0 >= B) return;

    const float4* x0 = reinterpret_cast<const float4*>(x + (size_t)row0 * IN_DIM) + lane;
    const float4* x1 = x0 + (IN_DIM / 4);
    const float4* wp = reinterpret_cast<const float4*>(W1) + lane;

    float acc0[NE], acc1[NE];
    #pragma unroll
    for (int e = 0; e < NE; ++e) { acc0[e] = 0.0f; acc1[e] = 0.0f; }

    // Round-8 proven loop: 16 chunks of 128 columns, unroll 4 so ptxas
    // front-batches 8 LDG.128 x-loads per body. DO NOT add asm here.
    #pragma unroll 4
    for (int c = 0; c < IN_DIM / 128; ++c) {
        float4 a0 = __ldcs(x0 + c * 32);     // stream x: keep W1 in L1
        float4 a1 = __ldcs(x1 + c * 32);
        #pragma unroll
        for (int e = 0; e < NE; ++e) {
            float4 w = __ldg(wp + e * (IN_DIM / 4) + c * 32);   // W1 L1-resident
            acc0[e] = fmaf(a0.x, w.x, fmaf(a0.y, w.y,
                      fmaf(a0.z, w.z, fmaf(a0.w, w.w, acc0[e]))));
            acc1[e] = fmaf(a1.x, w.x, fmaf(a1.y, w.y,
                      fmaf(a1.z, w.z, fmaf(a1.w, w.w, acc1[e]))));
        }
    }

    // Butterfly-reduce each accumulator across the warp (all lanes get sums).
    #pragma unroll
    for (int e = 0; e < NE; ++e) {
        #pragma unroll
        for (int off = 16; off > 0; off >>= 1) {
            acc0[e] += __shfl_xor_sync(0xffffffffu, acc0[e], off);
            acc1[e] += __shfl_xor_sync(0xffffffffu, acc1[e], off);
        }
    }

    // ==================== warp-parallel epilogue =========================
    // half-warp hw handles row row0+hw; lane le (0..15) owns expert le.
    const int hw = lane >> 4;
    const int le = lane & 15;
    const int row = row0 + hw;
    const unsigned FULL = 0xffffffffu;

    // Distribute: this lane's raw sum for expert le (predicated select tree).
    float sv = 0.0f;
    #pragma unroll
    for (int e = 0; e < NE; ++e)
        if (le == e) sv = hw ? acc1[e] : acc0[e];

    float h = tanhf(sv);

    // logits[le] = (sum_e h[e] * W2[le, e]) / 0.7 ; gather h via shfl.
    // Accumulation order e=0..15 matches the serial version bit-for-bit.
    float wr[NE];
    {
        const float4* W2v = reinterpret_cast<const float4*>(W2) + le * (NE / 4);
        #pragma unroll
        for (int q = 0; q < NE / 4; ++q) {
            float4 w = __ldg(W2v + q);
            wr[4 * q + 0] = w.x; wr[4 * q + 1] = w.y;
            wr[4 * q + 2] = w.z; wr[4 * q + 3] = w.w;
        }
    }
    float logit = 0.0f;
    const int hbase = hw << 4;
    #pragma unroll
    for (int e = 0; e < NE; ++e) {
        float he = __shfl_sync(FULL, h, hbase + e);
        logit = fmaf(he, wr[e], logit);
    }
    float v = logit / 0.7f;

    // Pack sort key: monotone-mapped float in high 32 bits, (15-idx) low
    // -> descending sort with ascending-index tie-break (stable argsort).
    unsigned iv = __float_as_uint(v);
    unsigned mk = iv ^ (unsigned)(((int)iv >> 31) | 0x80000000);
    u64 key = ((u64)mk << 32) | (unsigned)(15 - le);

    // Bitonic sort, descending, 16 lanes per half-warp (j <= 8 stays in-half).
    #pragma unroll
    for (int k2 = 2; k2 <= 16; k2 <<= 1) {
        #pragma unroll
        for (int j = k2 >> 1; j > 0; j >>= 1) {
            u64 other = __shfl_xor_sync(FULL, key, j);
            bool lowlane = ((le & j) == 0);
            bool dirup   = ((le & k2) == 0);
            bool wantMax = (lowlane == dirup);
            bool take = wantMax ? (other > key) : (other < key);
            if (take) key = other;
        }
    }

    // Unpack: lane le now holds the le-th largest logit + its expert index.
    int sidx = 15 - (int)(key & 0xFu);
    unsigned smk = (unsigned)(key >> 32);
    unsigned siv = (smk & 0x80000000u) ? (smk ^ 0x80000000u) : ~smk;
    float sval = __uint_as_float(siv);

    // Softmax over sorted logits (max lives at lane hbase).
    float m = __shfl_sync(FULL, sval, hbase);
    float p = expf(sval - m);
    float ssum = p;
    #pragma unroll
    for (int off = 8; off > 0; off >>= 1)
        ssum += __shfl_xor_sync(FULL, ssum, off);   // within-half butterfly
    p *= (1.0f / ssum);

    // Inclusive cumsum within half-warp.
    float cum = p;
    #pragma unroll
    for (int off = 1; off < 16; off <<= 1) {
        float t = __shfl_up_sync(FULL, cum, off);
        if (le >= off) cum += t;
    }

    // k = first position where cum >= 0.92 (else 16).
    unsigned bal = __ballot_sync(FULL, cum >= 0.92f);
    unsigned half_mask = (bal >> (hw << 4)) & 0xFFFFu;
    int k = half_mask ? __ffs(half_mask) : NE;

    float p1 = __shfl_sync(FULL, p, hbase + 0);
    float p2 = __shfl_sync(FULL, p, hbase + 1);
    float p3 = __shfl_sync(FULL, p, hbase + 2);
    if (p1 >= 0.46f && (p1 - p2) >= 0.1f) k = 1;
    if (k > 2 && ((p1 + p2) >= 0.82f || p3 <= 0.12f || (p2 - p3) <= 0.03f)) k = 2;
    if (k < 1) k = 1;
    if (k > 3) k = 3;

    // Outputs: lanes 0-7 of each half write the 8-wide rows; lane 0 writes k.
    float* oidx  = out;
    float* osc   = out + (size_t)B * 8;
    float* omask = out + (size_t)B * 16;
    float* okv   = out + (size_t)B * 24;
    if (le < 8) {
        float msk = (le < k) ? 1.0f : 0.0f;
        oidx[row * 8 + le]  = (float)sidx;
        osc[row * 8 + le]   = p * msk;
        omask[row * 8 + le] = msk;
        if (le == 0) okv[row] = (float)k;
    }
}

extern "C" void kernel_launch(void* const* d_in, const int* in_sizes, int n_in,
                              void* d_out, int out_size)
{
    const float* x  = (const float*)d_in[0];
    const float* W1 = (const float*)d_in[1];
    const float* W2 = (const float*)d_in[2];
    float* out = (float*)d_out;

    int B = in_sizes[0] / IN_DIM;                 // 16384

    // 4 warps/block, 2 rows/warp -> 8 rows/block.
    int blocks = (B + 7) / 8;                     // 2048
    gate_kernel<<<blocks, 128>>>(x, W1, W2, out, B);
}